// round 11
// baseline (speedup 1.0000x reference)
#include <cuda_runtime.h>
#include <cstdint>

#define NSTATES 35
#define NB      64
#define TT      512
#define DDIM    2496
#define BTROWS  (NB * TT)   // 32768
#define KC      64
#define NCH     39          // 2496/64
#define CPT     36          // columns per chunk (35 + 1 zero pad)
#define NCHK    16          // chunks per batch (32 steps each; last = 31)

typedef unsigned long long ull;

// Scratch (no cudaMalloc). +1 pad row so scan's last prefetch stays in-bounds.
__device__ float g_w[(size_t)(BTROWS + 1) * 40];        // emission weights, 40-padded
__device__ float g_P[(size_t)NB * NCHK * CPT * 40];     // chunk product matrices
__device__ float g_xsqp[NB][16];                        // per-batch |x|^2 partials

// ---------------------------------------------------------------------------
// helpers
// ---------------------------------------------------------------------------
__device__ __forceinline__ uint32_t smem_u32(const void* p) {
    return (uint32_t)__cvta_generic_to_shared(p);
}
__device__ __forceinline__ uint32_t cvt_bf2(float lo, float hi) {
    uint32_t r;
    asm("cvt.rn.bf16x2.f32 %0, %1, %2;" : "=r"(r) : "f"(hi), "f"(lo));
    return r;
}
__device__ __forceinline__ void mma_bf16(float* d,
    uint32_t a0, uint32_t a1, uint32_t a2, uint32_t a3, uint32_t b0, uint32_t b1) {
    asm volatile(
        "mma.sync.aligned.m16n8k16.row.col.f32.bf16.bf16.f32 "
        "{%0,%1,%2,%3}, {%4,%5,%6,%7}, {%8,%9}, {%0,%1,%2,%3};\n"
        : "+f"(d[0]), "+f"(d[1]), "+f"(d[2]), "+f"(d[3])
        : "r"(a0), "r"(a1), "r"(a2), "r"(a3), "r"(b0), "r"(b1));
}
__device__ __forceinline__ void ldsm4(uint32_t* r, uint32_t a) {
    asm volatile("ldmatrix.sync.aligned.m8n8.x4.shared.b16 {%0,%1,%2,%3}, [%4];"
        : "=r"(r[0]), "=r"(r[1]), "=r"(r[2]), "=r"(r[3]) : "r"(a));
}
__device__ __forceinline__ void ldsm2(uint32_t* r, uint32_t a) {
    asm volatile("ldmatrix.sync.aligned.m8n8.x2.shared.b16 {%0,%1}, [%2];"
        : "=r"(r[0]), "=r"(r[1]) : "r"(a));
}
__device__ __forceinline__ void sts64(uint32_t addr, uint32_t a, uint32_t b) {
    asm volatile("st.shared.v2.b32 [%0], {%1,%2};" :: "r"(addr), "r"(a), "r"(b));
}
__device__ __forceinline__ float bfly_sum32(float v) {
    const unsigned FULL = 0xffffffffu;
    v += __shfl_xor_sync(FULL, v, 16);
    v += __shfl_xor_sync(FULL, v, 8);
    v += __shfl_xor_sync(FULL, v, 4);
    v += __shfl_xor_sync(FULL, v, 2);
    v += __shfl_xor_sync(FULL, v, 1);
    return v;
}

// ---- f32x2 packed fp32 (exact; two fp32 lanes per instruction) ----
__device__ __forceinline__ ull packf2(float lo, float hi) {
    ull r; asm("mov.b64 %0, {%1, %2};" : "=l"(r) : "f"(lo), "f"(hi)); return r;
}
__device__ __forceinline__ void unpackf2(float& lo, float& hi, ull v) {
    asm("mov.b64 {%0, %1}, %2;" : "=f"(lo), "=f"(hi) : "l"(v));
}
__device__ __forceinline__ float lof(ull v) { float a, b; unpackf2(a, b, v); return a; }
__device__ __forceinline__ float hif(ull v) { float a, b; unpackf2(a, b, v); return b; }
__device__ __forceinline__ ull fma2(ull a, ull b, ull c) {
    ull r; asm("fma.rn.f32x2 %0, %1, %2, %3;" : "=l"(r) : "l"(a), "l"(b), "l"(c)); return r;
}
__device__ __forceinline__ ull mul2(ull a, ull b) {
    ull r; asm("mul.rn.f32x2 %0, %1, %2;" : "=l"(r) : "l"(a), "l"(b)); return r;
}
__device__ __forceinline__ ull add2(ull a, ull b) {
    ull r; asm("add.rn.f32x2 %0, %1, %2;" : "=l"(r) : "l"(a), "l"(b)); return r;
}

// ---------------------------------------------------------------------------
// GEMM: smem-staged bf16 m16n8k16, double-buffered, one sync per chunk.
// __launch_bounds__(128, 3): cap ~170 regs -> 3 CTAs/SM -> +50% load MLP.
// ---------------------------------------------------------------------------
__global__ void __launch_bounds__(128, 3) k_gemm(const float* __restrict__ x,
                                                 const float* __restrict__ mM) {
    // A0 @0 (16K) | A1 @16384 | B0 @32768 (5K) | B1 @37888 ; total 43008
    __shared__ __align__(16) unsigned char smraw[43008];
    __shared__ float msq[40];
    const int tid = threadIdx.x, wid = tid >> 5, lane = tid & 31;
    const int wstart = wid * 32;
    const int hhalf = lane >> 4;
    const int l4 = lane & 15;
    const int xl = lane & 7;
    const int rowBase = blockIdx.x * 128;
    const uint32_t smA = smem_u32(smraw);
    const uint32_t smB = smA + 32768;

    const uint32_t aAddr0 = smA + (uint32_t)(wstart + 0 * 16 + l4) * 128;
    const uint32_t aAddr1 = smA + (uint32_t)(wstart + 1 * 16 + l4) * 128;
    uint32_t bAddr[5];
#pragma unroll
    for (int nt = 0; nt < 5; nt++) bAddr[nt] = smB + (uint32_t)(nt * 8 + xl) * 128;
    const int hvA = hhalf;
    const int hvB = (lane >> 3) & 1;

    float acc[2][5][4];
#pragma unroll
    for (int mt = 0; mt < 2; mt++)
#pragma unroll
        for (int nt = 0; nt < 5; nt++)
#pragma unroll
            for (int i = 0; i < 4; i++) acc[mt][nt][i] = 0.f;

    float xa0 = 0.f, xa1 = 0.f, xa2 = 0.f, xa3 = 0.f;
    float bacc[5] = {0.f, 0.f, 0.f, 0.f, 0.f};
    float4 av[16], bvf[5];

#define LOADCHUNK(CH) do {                                                      \
    int kc0 = (CH) * KC;                                                        \
    _Pragma("unroll")                                                           \
    for (int i = 0; i < 16; i++) {                                              \
        int r = wstart + i * 2 + hhalf;                                         \
        av[i] = *(const float4*)(x + (size_t)(rowBase + r) * DDIM + kc0 + l4*4);\
    }                                                                           \
    _Pragma("unroll")                                                           \
    for (int k = 0; k < 5; k++) {                                               \
        int s = (wid + 4 * k) * 2 + hhalf;                                      \
        int ss = s < NSTATES ? s : NSTATES - 1;                                 \
        float4 t = *(const float4*)(mM + (size_t)ss * DDIM + kc0 + l4 * 4);     \
        if (s >= NSTATES) { t.x = 0.f; t.y = 0.f; t.z = 0.f; t.w = 0.f; }       \
        bvf[k] = t;                                                             \
    } } while (0)

#define CVTSTS(AOFF, BOFF) do {                                                 \
    _Pragma("unroll")                                                           \
    for (int i = 0; i < 16; i++) {                                              \
        int sr = wstart + i * 2 + hhalf;                                        \
        float4 v = av[i];                                                       \
        xa0 = fmaf(v.x, v.x, xa0); xa1 = fmaf(v.y, v.y, xa1);                   \
        xa2 = fmaf(v.z, v.z, xa2); xa3 = fmaf(v.w, v.w, xa3);                   \
        uint32_t lo = cvt_bf2(v.x, v.y), hi = cvt_bf2(v.z, v.w);                \
        uint32_t ad = smA + (AOFF) + (uint32_t)sr * 128                         \
                    + (uint32_t)((((l4 >> 1) ^ (sr & 7)) << 4) + ((l4 & 1) << 3)); \
        sts64(ad, lo, hi);                                                      \
    }                                                                           \
    _Pragma("unroll")                                                           \
    for (int k = 0; k < 5; k++) {                                               \
        int s = (wid + 4 * k) * 2 + hhalf;                                      \
        float4 v = bvf[k];                                                      \
        bacc[k] = fmaf(v.x, v.x, fmaf(v.y, v.y, fmaf(v.z, v.z,                  \
                  fmaf(v.w, v.w, bacc[k]))));                                   \
        uint32_t lo = cvt_bf2(v.x, v.y), hi = cvt_bf2(v.z, v.w);                \
        uint32_t ad = smB + (BOFF) + (uint32_t)s * 128                          \
                    + (uint32_t)((((l4 >> 1) ^ (s & 7)) << 4) + ((l4 & 1) << 3)); \
        sts64(ad, lo, hi);                                                      \
    } } while (0)

#define MMASEC(AOFF, BOFF) do {                                                 \
    _Pragma("unroll")                                                           \
    for (int kt = 0; kt < 4; kt++) {                                            \
        uint32_t A0[4], A1[4];                                                  \
        uint32_t offA = (AOFF) + (uint32_t)(((kt * 2 + hvA) ^ xl) << 4);        \
        ldsm4(A0, aAddr0 + offA);                                               \
        ldsm4(A1, aAddr1 + offA);                                               \
        uint32_t offB = (BOFF) + (uint32_t)(((kt * 2 + hvB) ^ xl) << 4);        \
        _Pragma("unroll")                                                       \
        for (int nt = 0; nt < 5; nt++) {                                        \
            uint32_t B[2];                                                      \
            ldsm2(B, bAddr[nt] + offB);                                         \
            mma_bf16(acc[0][nt], A0[0], A0[1], A0[2], A0[3], B[0], B[1]);       \
            mma_bf16(acc[1][nt], A1[0], A1[1], A1[2], A1[3], B[0], B[1]);       \
        }                                                                       \
    } } while (0)

    LOADCHUNK(0);
    CVTSTS(0u, 0u);
    __syncthreads();

    for (int ch = 0; ch < NCH; ch++) {
        uint32_t aCur = (ch & 1) ? 16384u : 0u;
        uint32_t bCur = (ch & 1) ? 5120u : 0u;
        uint32_t aNxt = (ch & 1) ? 0u : 16384u;
        uint32_t bNxt = (ch & 1) ? 0u : 5120u;
        bool more = (ch + 1 < NCH);
        if (more) LOADCHUNK(ch + 1);
        MMASEC(aCur, bCur);
        if (more) CVTSTS(aNxt, bNxt);
        __syncthreads();
    }

    // exact fp32 m_sq
#pragma unroll
    for (int k = 0; k < 5; k++) {
        float v = bacc[k];
        v += __shfl_xor_sync(0xffffffffu, v, 1);
        v += __shfl_xor_sync(0xffffffffu, v, 2);
        v += __shfl_xor_sync(0xffffffffu, v, 4);
        v += __shfl_xor_sync(0xffffffffu, v, 8);
        int s = (wid + 4 * k) * 2 + hhalf;
        if (l4 == 0) msq[s] = v;
    }
    __syncthreads();

    // epilogue: w stored to g_w[bt][40], pads zero
    const float NEG_INV = -1.0f / 500.0f;
    const int g = lane >> 2, c2 = lane & 3;
#pragma unroll
    for (int mt = 0; mt < 2; mt++) {
#pragma unroll
        for (int h = 0; h < 2; h++) {
            int row = rowBase + wstart + mt * 16 + g + h * 8;
#pragma unroll
            for (int nt = 0; nt < 5; nt++) {
                int col = nt * 8 + 2 * c2;
                float v0 = acc[mt][nt][2 * h + 0];
                float v1 = acc[mt][nt][2 * h + 1];
                float w0 = (col     < NSTATES) ? __expf((msq[col]     - 2.f * v0) * NEG_INV) : 0.f;
                float w1 = (col + 1 < NSTATES) ? __expf((msq[col + 1] - 2.f * v1) * NEG_INV) : 0.f;
                *(float2*)&g_w[(size_t)row * 40 + col] = make_float2(w0, w1);
            }
        }
    }

    float tot = bfly_sum32(xa0 + xa1 + xa2 + xa3);
    if (lane == 0)
        g_xsqp[(rowBase + wstart) >> 9][(blockIdx.x * 4 + wid) & 15] = tot;
}

// ---------------------------------------------------------------------------
// Phase 1: chunked scan, f32x2-packed (exact fp32, 2 states per instruction).
// States 0..35 (35 = pad, w=0) in 18 reg-pairs P[k] = (p_2k, p_2k+1).
// Shift-by-2 operand = P[k-1] directly; shift-by-1 = pack(hi(P[k-1]), lo(P[k])).
// Constants EXACTLY 4x true values; 511*ln4 subtracted in k_comb.
// ---------------------------------------------------------------------------
__global__ void __launch_bounds__(288) k_scan() {
    const int tid = threadIdx.x;
    const int cid = blockIdx.x * 8 + tid / CPT;   // 0..1023
    const int col = tid % CPT;                    // 0..35 (35 = zero column)
    const int b = cid >> 4, c = cid & 15;
    const int nsteps = (c == 15) ? 31 : 32;
    const float* wr = g_w + ((size_t)b * TT + 32 * c + 1) * 40;
    const float EPS4 = (0.02f / 35.0f) * 4.0f;
    const ull C1x2 = packf2(0.4f,  0.4f);    // 0.1 * 4
    const ull C2x2 = packf2(3.2f,  3.2f);    // 0.8 * 4
    const ull C3x2 = packf2(0.32f, 0.32f);   // 0.08 * 4

    ull P[18];
#pragma unroll
    for (int k = 0; k < 18; k++) P[k] = 0ull;
    float S = 0.f;
    if (col < NSTATES) {
        // set the right half of pair col>>1 to 1.0
        float lo = (col & 1) ? 0.f : 1.f;
        float hi = (col & 1) ? 1.f : 0.f;
        P[col >> 1] = packf2(lo, hi);
        S = 1.f;
    }

    // prefetch row for step 0 (9 x 16B = 36 w's; pads give w[35]=0)
    ulonglong2 nv[9];
#pragma unroll
    for (int k = 0; k < 9; k++) nv[k] = __ldg((const ulonglong2*)wr + k);

#pragma unroll 1
    for (int s = 0; s < nsteps; s++) {
        ull W[18];
#pragma unroll
        for (int m = 0; m < 9; m++) { W[2 * m] = nv[m].x; W[2 * m + 1] = nv[m].y; }
        wr += 40;
#pragma unroll
        for (int k = 0; k < 9; k++) nv[k] = __ldg((const ulonglong2*)wr + k);

        float sigma = EPS4 * S;
        ull sig2 = packf2(sigma, sigma);
        float oldP33 = hif(P[16]);
        float oldP34 = lof(P[17]);

#pragma unroll
        for (int k = 17; k >= 1; k--) {
            ull M = packf2(hif(P[k - 1]), lof(P[k]));   // (p_{2k-1}, p_{2k})
            ull T = fma2(C3x2, P[k - 1], sig2);         // C3*(p_{2k-2},p_{2k-1}) + sig
            T = fma2(C2x2, M, T);
            T = fma2(C1x2, P[k], T);
            P[k] = mul2(W[k], T);
        }
        {   // pair 0: wrap over 35 states (p_{-1}=p34, p_{-2}=p33, old values)
            ull M   = packf2(oldP34, lof(P[0]));        // (p34, p0)
            ull Mm2 = packf2(oldP33, oldP34);           // (p33, p34)
            ull T = fma2(C3x2, Mm2, sig2);
            T = fma2(C2x2, M, T);
            T = fma2(C1x2, P[0], T);
            P[0] = mul2(W[0], T);
        }

        // S = sum of all 36 packed states (p35 = 0)
        ull a0 = add2(add2(P[0],  P[1]),  add2(P[2],  P[3]));
        ull a1 = add2(add2(P[4],  P[5]),  add2(P[6],  P[7]));
        ull a2 = add2(add2(P[8],  P[9]),  add2(P[10], P[11]));
        ull a3 = add2(add2(P[12], P[13]), add2(P[14], P[15]));
        ull a4 = add2(P[16], P[17]);
        ull t = add2(add2(a0, a1), add2(a2, a3));
        t = add2(t, a4);
        float slo, shi;
        unpackf2(slo, shi, t);
        S = slo + shi;
    }

    // store column (40 floats: 36 packed incl. p35=0, + 4 zero pad)
    float* dst = g_P + ((size_t)cid * CPT + col) * 40;
#pragma unroll
    for (int k = 0; k < 9; k++)
        *((ulonglong2*)dst + k) = make_ulonglong2(P[2 * k], P[2 * k + 1]);
    *(float4*)(dst + 36) = make_float4(0.f, 0.f, 0.f, 0.f);
}

// ---------------------------------------------------------------------------
// Phase 2: per-batch combine. 40 threads; thread i owns output row i.
// v <- P_c v with per-chunk renorm; out = Cacc + xoff - 511*ln4.
// ---------------------------------------------------------------------------
__global__ void k_comb(float* __restrict__ out) {
    __shared__ float vsh[40];
    __shared__ float ush[40];
    const int b = blockIdx.x;
    const int i = threadIdx.x;   // 0..39
    const float NEG_INV = -1.0f / 500.0f;
    const float LOGCORR = 708.39641853f;   // 511 * ln(4)

    float xoff = 0.f;
#pragma unroll
    for (int k = 0; k < 16; k++) xoff += g_xsqp[b][k];
    xoff *= NEG_INV;

    const float EXPM20 = 2.0611536e-09f;
    float w0 = g_w[(size_t)b * TT * 40 + i];   // pads are 0
    vsh[i] = (i == 0) ? w0 : w0 * EXPM20;
    __syncthreads();

    float Cacc = 10.0f;
    for (int c = 0; c < NCHK; c++) {
        const float* Pc = g_P + (size_t)(b * NCHK + c) * CPT * 40;
        float acc = 0.f;
#pragma unroll 7
        for (int j = 0; j < NSTATES; j++)
            acc = fmaf(__ldg(Pc + j * 40 + i), vsh[j], acc);
        ush[i] = acc;
        __syncthreads();
        float Ssum = 0.f;
#pragma unroll
        for (int k = 0; k < 40; k += 4) {
            float4 t = *(const float4*)&ush[k];
            Ssum += (t.x + t.y) + (t.z + t.w);
        }
        float rs = __fdividef(1.0f, Ssum);
        Cacc += __logf(Ssum);
        vsh[i] = acc * rs;
        __syncthreads();
    }
    if (i == 0) out[b] = Cacc + xoff - LOGCORR;
}

// ---------------------------------------------------------------------------
extern "C" void kernel_launch(void* const* d_in, const int* in_sizes, int n_in,
                              void* d_out, int out_size) {
    const float* obs = (const float*)d_in[0];  // [64,512,16,13,12]
    const float* m   = (const float*)d_in[1];  // [35,16,13,12]
    float* out = (float*)d_out;                // [64]

    k_gemm<<<BTROWS / 128, 128>>>(obs, m);     // 256 CTAs
    k_scan<<<NB * NCHK / 8, 8 * CPT>>>();      // 128 CTAs x 288 thr
    k_comb<<<NB, 40>>>(out);
}